// round 14
// baseline (speedup 1.0000x reference)
#include <cuda_runtime.h>

// Nosé–Hoover chain (N_CHAIN=2) velocity-Verlet, B=1024, NDOF=64, 200 steps.
// Out: [traj_x (201,1024,64) | traj_v (201,1024,64)] fp32.
//
// R14 = R5 kernel (best: register-resident fused loop, 2 systems/warp,
// 16 lanes/system, moments recursion, f32x2 packed map, STG.128 from packed
// regs, const-specialized kT=mass=Q=1 fast path) with ONE change:
// launch shape 64 blocks x 256 threads (was 128 x 128). 512 warps packed
// 8/SM on 64 SMs = 2 warps per SMSP -> the ~60% exposed chain-latency
// cycles (issue was 41%) are filled by the co-resident warp. Per-SMSP fma
// pipe (~25% busy in R5) has headroom for both warps; LTS store floor
// (~105MB) becomes the binding constraint.

namespace {
constexpr int kB     = 1024;
constexpr int kNdof  = 64;
constexpr int kSteps = 200;
constexpr int kF4Sys = kNdof / 4;           // 16 float4 per system
constexpr int kF4Tot = kB * kF4Sys;         // 16384 float4 per snapshot
}

#define FMA2(d,a,b,c) asm("fma.rn.f32x2 %0,%1,%2,%3;" : "=l"(d) : "l"(a), "l"(b), "l"(c))
#define MUL2(d,a,b)   asm("mul.rn.f32x2 %0,%1,%2;"    : "=l"(d) : "l"(a), "l"(b))
#define PACK2(d,f)    asm("mov.b64 %0,{%1,%1};"       : "=l"(d) : "f"(f))
#define PACKAB(d,a,b) asm("mov.b64 %0,{%1,%2};"       : "=l"(d) : "f"(a), "f"(b))
#define STG128(p,off,a,b) \
    asm volatile("st.global.v2.b64 [%0+" #off "],{%1,%2};" :: "l"(p), "l"(a), "l"(b) : "memory")

// exp(-z) for |z| <= ~3e-4: 1 - z + z^2/2  (rel err ~ z^3/6 <= 5e-12)
__device__ __forceinline__ float expm(float z) {
    return fmaf(fmaf(0.5f, z, -1.0f), z, 1.0f);
}

// Full 200-step loop; with literal kT/mass/Q all coefficients constant-fold
// into FFMA immediates.
__device__ __forceinline__ void nhc_loop(
    float kT, float mass, float Q,
    float sxx, float sxv, float svv,
    unsigned long long Xp0, unsigned long long Xp1,
    unsigned long long Vp0, unsigned long long Vp1,
    const float4* pxc, const float4* pvc)
{
    const float dt    = 0.002f;
    const float dt4   = 0.25f  * dt;
    const float dt8   = 0.125f * dt;
    const float dth   = 0.5f   * dt;
    const float invQ  = 1.0f / Q;
    const float c1    = dth / mass;                  // verlet half-kick coeff
    const float A     = 1.0f - dt * c1;              // constant x coefficient
    const float A2    = A * A;
    const float cx0   = -c1 * (1.0f + A);            // Cx = cx0 * sv
    const float mIQ   = mass * invQ;
    const float nkIQ  = -(float)kNdof * kT * invQ;
    const float kTiQ  = kT * invQ;
    const float m0c   = cx0 * cx0;                   // svv' coeffs
    const float m1c   = 2.0f * cx0 * A;
    const float p1c   = 2.0f * A * dt;               // sxx' coeffs
    const float p2c   = dt * dt;
    const float acx   = A * cx0;                     // sxv' coeffs
    const float mc    = A2 + dt * cx0;               // A*Cv + B*Cx = mc * sv2
    const float dA    = dt * A;

    unsigned long long Ap;
    PACK2(Ap, A);

    float xi0 = 0.0f, xi1 = 0.0f;

    for (int step = 0; step < kSteps; step += 2) {
        #pragma unroll
        for (int u = 0; u < 2; ++u) {
            // ---- first half chain ----
            float G  = fmaf(mIQ, svv, nkIQ);
            xi1 = fmaf(dt4, G, xi1);
            float G0 = fmaf(xi0, xi0, -kTiQ);
            float z1 = xi1 * dt8;
            float s  = expm(z1);
            float s2 = s * s;
            float dt4s = dt4 * s;
            float xi0a = fmaf(xi0, s2, G0 * dt4s);
            float z0 = xi0a * dth;
            float sv  = expm(z0);
            float sv2 = sv * sv;

            // ---- Svv' (only sv/sv2 on the critical path) ----
            float m0 = m0c * sxx;
            float m1 = m1c * sxv;
            float m2 = A2  * svv;
            float svv_n = sv2 * fmaf(sv2, m2, fmaf(sv, m1, m0));

            // ---- second half chain ----
            float G2 = fmaf(mIQ, svv_n, nkIQ);
            xi0 = fmaf(dt4s, G2, xi0a * s2);
            float G3 = fmaf(xi0, xi0, -kTiQ);
            xi1 = fmaf(dt4, G3, xi1);

            // ---- remaining moments ----
            float sxx_n = fmaf(p2c * sv2, svv, fmaf(p1c * sv, sxv, A2 * sxx));
            float t    = acx * sv;                     // A*Cx
            float midm = mc * sv2;                     // A*Cv + B*Cx
            float bcv  = (dA * sv) * sv2;              // B*Cv
            float sxv_n = fmaf(bcv, svv, fmaf(midm, sxv, t * sxx));
            sxx = sxx_n; sxv = sxv_n; svv = svv_n;

            // ---- elementwise linear map (f32x2) ----
            float B  = dt  * sv;
            float Cx = cx0 * sv;
            float Cv = A   * sv2;
            unsigned long long Bp, Cxp, Cvp, t0, t1, u0, u1, xn0, xn1, vn0, vn1;
            PACK2(Bp, B); PACK2(Cxp, Cx); PACK2(Cvp, Cv);
            MUL2(t0, Bp,  Vp0);  MUL2(t1, Bp,  Vp1);
            MUL2(u0, Cvp, Vp0);  MUL2(u1, Cvp, Vp1);
            FMA2(xn0, Ap,  Xp0, t0);  FMA2(xn1, Ap,  Xp1, t1);
            FMA2(vn0, Cxp, Xp0, u0);  FMA2(vn1, Cxp, Xp1, u1);
            Xp0 = xn0; Xp1 = xn1; Vp0 = vn0; Vp1 = vn1;

            // ---- trajectory stores ----
            if (u == 0) {
                STG128(pxc, 0, Xp0, Xp1);
                STG128(pvc, 0, Vp0, Vp1);
            } else {
                STG128(pxc, 262144, Xp0, Xp1);   // + one snapshot (bytes)
                STG128(pvc, 262144, Vp0, Vp1);
            }
        }
        pxc += 2 * kF4Tot; pvc += 2 * kF4Tot;
    }
}

__global__ __launch_bounds__(256, 1)
void nhc_kernel(const float4* __restrict__ gx0,
                const float4* __restrict__ gv0,
                const float*  __restrict__ pkT,
                const float*  __restrict__ pmass,
                const float*  __restrict__ pQ,
                float4*       __restrict__ out)
{
    const int tid = threadIdx.x;
    const int ls  = tid & 15;                        // lane-in-system
    const int b   = blockIdx.x * 16 + (tid >> 4);    // system id < 1024

    const float kT   = *pkT;
    const float mass = *pmass;
    const float Q    = *pQ;

    const int idx = b * kF4Sys + ls;                 // float4 slot

    const float4 x0 = gx0[idx];
    const float4 v0 = gv0[idx];

    const float4* pxc = out + idx;
    const float4* pvc = out + (size_t)(kSteps + 1) * kF4Tot + idx;

    // ---- initial moments (one-time 16-lane reduction) ----
    float sxx, sxv, svv;
    {
        float a = x0.x * x0.x; a = fmaf(x0.y, x0.y, a); a = fmaf(x0.z, x0.z, a); a = fmaf(x0.w, x0.w, a);
        float c = x0.x * v0.x; c = fmaf(x0.y, v0.y, c); c = fmaf(x0.z, v0.z, c); c = fmaf(x0.w, v0.w, c);
        float e = v0.x * v0.x; e = fmaf(v0.y, v0.y, e); e = fmaf(v0.z, v0.z, e); e = fmaf(v0.w, v0.w, e);
        #pragma unroll
        for (int m = 1; m <= 8; m <<= 1) {
            a += __shfl_xor_sync(0xffffffffu, a, m);
            c += __shfl_xor_sync(0xffffffffu, c, m);
            e += __shfl_xor_sync(0xffffffffu, e, m);
        }
        sxx = a; sxv = c; svv = e;
    }

    // ---- pack state ----
    unsigned long long Xp0, Xp1, Vp0, Vp1;
    PACKAB(Xp0, x0.x, x0.y); PACKAB(Xp1, x0.z, x0.w);
    PACKAB(Vp0, v0.x, v0.y); PACKAB(Vp1, v0.z, v0.w);

    // step-0 snapshot
    STG128(pxc, 0, Xp0, Xp1);
    STG128(pvc, 0, Vp0, Vp1);
    pxc += kF4Tot; pvc += kF4Tot;

    // ---- uniform dispatch: literal-constant fast path vs general ----
    if (kT == 1.0f && mass == 1.0f && Q == 1.0f) {
        nhc_loop(1.0f, 1.0f, 1.0f, sxx, sxv, svv, Xp0, Xp1, Vp0, Vp1, pxc, pvc);
    } else {
        nhc_loop(kT, mass, Q, sxx, sxv, svv, Xp0, Xp1, Vp0, Vp1, pxc, pvc);
    }
}

extern "C" void kernel_launch(void* const* d_in, const int* in_sizes, int n_in,
                              void* d_out, int out_size)
{
    const float4* x0   = (const float4*)d_in[0];
    const float4* v0   = (const float4*)d_in[1];
    const float*  kT   = (const float*)d_in[2];
    const float*  mass = (const float*)d_in[3];
    const float*  Q    = (const float*)d_in[4];
    float4* out = (float4*)d_out;

    // 1024 systems, 2/warp -> 512 warps; 64 blocks x 256 threads:
    // 8 warps/SM on 64 SMs = 2 warps per SMSP (latency hiding)
    nhc_kernel<<<kB / 16, 256>>>(x0, v0, kT, mass, Q, out);
}

// round 15
// speedup vs baseline: 1.5000x; 1.5000x over previous
#include <cuda_runtime.h>

// Nosé–Hoover chain (N_CHAIN=2) velocity-Verlet, B=1024, NDOF=64, 200 steps.
// Out: [traj_x (201,1024,64) | traj_v (201,1024,64)] fp32.
//
// R15: warp-specialized producer/consumer INSIDE each block (smem+bar.sync;
// the R6 global-flag and R7 sv-from-L2 handoffs both failed, and R14 proved
// co-resident full-chain warps don't interleave).
//  Block = 160 thr: warps 0-3 = consumers (2 systems each, 16 lanes/sys,
//  4 dof/lane f32x2); warp 4 = producer (lanes 0-7 run the 8 systems'
//  thermostat chains SIMT via the closed 3-moment recursion).
//  Producer emits sv[step] into double-buffered smem (batches of 10 steps,
//  one __syncthreads per batch). Consumers do NO chain: LDS sv (2-way
//  broadcast), 7 scalar coeffs, 8 packed f32x2 ops, 2x STG.128 per step.
//  Consumers compute the initial moments (they already load x0/v0) and pass
//  them to the producer through smem.
// Floors: producer serial ~6us (overlapped); chip LTS stores ~8.3us binding.

namespace {
constexpr int NSYS   = 1024;
constexpr int NSTEP  = 200;
constexpr int BATCH  = 10;
constexpr int NBATCH = NSTEP / BATCH;       // 20
constexpr int SPB    = 8;                   // systems per block
constexpr int F4SYS  = 16;                  // float4 per system
constexpr int F4SNAP = NSYS * F4SYS;        // 16384 float4 per snapshot
}

#define FMA2(d,a,b,c) asm("fma.rn.f32x2 %0,%1,%2,%3;" : "=l"(d) : "l"(a), "l"(b), "l"(c))
#define MUL2(d,a,b)   asm("mul.rn.f32x2 %0,%1,%2;"    : "=l"(d) : "l"(a), "l"(b))
#define PACK2(d,f)    asm("mov.b64 %0,{%1,%1};"       : "=l"(d) : "f"(f))
#define PACKAB(d,a,b) asm("mov.b64 %0,{%1,%2};"       : "=l"(d) : "f"(a), "f"(b))
#define STG128(p,a,b) \
    asm volatile("st.global.v2.b64 [%0],{%1,%2};" :: "l"(p), "l"(a), "l"(b) : "memory")

// exp(-z) for |z| <= ~3e-4: 1 - z + z^2/2  (rel err ~ z^3/6 <= 5e-12)
__device__ __forceinline__ float expm(float z) {
    return fmaf(fmaf(0.5f, z, -1.0f), z, 1.0f);
}

__device__ __forceinline__ void run_block(
    float kT, float mass, float Q,
    int wid, int lane, int base,
    const float4* __restrict__ gx0,
    const float4* __restrict__ gv0,
    float4* __restrict__ out,
    float (*s_mom)[4],
    float (*s_sv)[BATCH][SPB])
{
    const float dt   = 0.002f;
    const float dt4  = 0.25f  * dt;
    const float dt8  = 0.125f * dt;
    const float dth  = 0.5f   * dt;
    const float invQ = 1.0f / Q;
    const float c1   = dth / mass;
    const float A    = 1.0f - dt * c1;
    const float A2   = A * A;
    const float cx0  = -c1 * (1.0f + A);
    const float mIQ  = mass * invQ;
    const float nkIQ = -64.0f * kT * invQ;
    const float kTiQ = kT * invQ;
    const float m0c  = cx0 * cx0;
    const float m1c  = 2.0f * cx0 * A;
    const float p1c  = 2.0f * A * dt;
    const float p2c  = dt * dt;
    const float acx  = A * cx0;
    const float mc   = A2 + dt * cx0;
    const float dA   = dt * A;

    // ---- consumer state ----
    unsigned long long Xp0 = 0, Xp1 = 0, Vp0 = 0, Vp1 = 0, Ap = 0;
    const float4* px = nullptr;
    const float4* pv = nullptr;
    int sysloc = 0;

    // ---- producer state ----
    float sxx = 0.0f, sxv = 0.0f, svv = 0.0f, xi0 = 0.0f, xi1 = 0.0f;

    if (wid < 4) {
        // ========== consumer setup: load, moments, snapshot 0 ==========
        sysloc = 2 * wid + (lane >> 4);              // 0..7
        const int sys = base + sysloc;
        const int idx = sys * F4SYS + (lane & 15);
        const float4 x0 = gx0[idx];
        const float4 v0 = gv0[idx];

        float a = x0.x * x0.x; a = fmaf(x0.y, x0.y, a); a = fmaf(x0.z, x0.z, a); a = fmaf(x0.w, x0.w, a);
        float c = x0.x * v0.x; c = fmaf(x0.y, v0.y, c); c = fmaf(x0.z, v0.z, c); c = fmaf(x0.w, v0.w, c);
        float e = v0.x * v0.x; e = fmaf(v0.y, v0.y, e); e = fmaf(v0.z, v0.z, e); e = fmaf(v0.w, v0.w, e);
        #pragma unroll
        for (int m = 1; m <= 8; m <<= 1) {           // reduce within 16-lane group
            a += __shfl_xor_sync(0xffffffffu, a, m);
            c += __shfl_xor_sync(0xffffffffu, c, m);
            e += __shfl_xor_sync(0xffffffffu, e, m);
        }
        if ((lane & 15) == 0) {
            s_mom[sysloc][0] = a;
            s_mom[sysloc][1] = c;
            s_mom[sysloc][2] = e;
        }

        PACKAB(Xp0, x0.x, x0.y); PACKAB(Xp1, x0.z, x0.w);
        PACKAB(Vp0, v0.x, v0.y); PACKAB(Vp1, v0.z, v0.w);
        PACK2(Ap, A);

        px = out + idx;
        pv = out + (size_t)(NSTEP + 1) * F4SNAP + idx;
        STG128(px, Xp0, Xp1);
        STG128(pv, Vp0, Vp1);
        px += F4SNAP; pv += F4SNAP;
    }
    __syncthreads();                                  // moments visible

    if (wid == 4 && lane < SPB) {
        sxx = s_mom[lane][0];
        sxv = s_mom[lane][1];
        svv = s_mom[lane][2];
    }

    // one thermostat step for this lane's system; returns sv
    auto chain_step = [&]() -> float {
        float G  = fmaf(mIQ, svv, nkIQ);
        xi1 = fmaf(dt4, G, xi1);
        float G0 = fmaf(xi0, xi0, -kTiQ);
        float z1 = xi1 * dt8;
        float se = expm(z1);
        float s2 = se * se;
        float dt4s = dt4 * se;
        float xi0a = fmaf(xi0, s2, G0 * dt4s);
        float z0 = xi0a * dth;
        float sv  = expm(z0);
        float sv2 = sv * sv;
        float svv_n = sv2 * fmaf(sv2, A2 * svv, fmaf(sv, m1c * sxv, m0c * sxx));
        float G2 = fmaf(mIQ, svv_n, nkIQ);
        xi0 = fmaf(dt4s, G2, xi0a * s2);
        float G3 = fmaf(xi0, xi0, -kTiQ);
        xi1 = fmaf(dt4, G3, xi1);
        float sxx_n = fmaf(p2c * sv2, svv, fmaf(p1c * sv, sxv, A2 * sxx));
        float sxv_n = fmaf((dA * sv) * sv2, svv,
                           fmaf(mc * sv2, sxv, (acx * sv) * sxx));
        sxx = sxx_n; sxv = sxv_n; svv = svv_n;
        return sv;
    };

    // producer fills batch 0
    if (wid == 4 && lane < SPB) {
        #pragma unroll
        for (int k = 0; k < BATCH; ++k) {
            s_sv[0][k][lane] = chain_step();
        }
    }
    __syncthreads();                                  // batch 0 ready

    for (int b = 0; b < NBATCH; ++b) {
        const int ph = b & 1;
        if (wid < 4) {
            // ========== consume batch b ==========
            float svs[BATCH];
            #pragma unroll
            for (int k = 0; k < BATCH; ++k)
                svs[k] = s_sv[ph][k][sysloc];
            #pragma unroll
            for (int k = 0; k < BATCH; ++k) {
                float sv  = svs[k];
                float sv2 = sv * sv;
                float B   = dt  * sv;
                float Cx  = cx0 * sv;
                float Cv  = A   * sv2;
                unsigned long long Bp, Cxp, Cvp, t0, t1, u0, u1, xn0, xn1, vn0, vn1;
                PACK2(Bp, B); PACK2(Cxp, Cx); PACK2(Cvp, Cv);
                MUL2(t0, Bp,  Vp0);  MUL2(t1, Bp,  Vp1);
                MUL2(u0, Cvp, Vp0);  MUL2(u1, Cvp, Vp1);
                FMA2(xn0, Ap,  Xp0, t0);  FMA2(xn1, Ap,  Xp1, t1);
                FMA2(vn0, Cxp, Xp0, u0);  FMA2(vn1, Cxp, Xp1, u1);
                Xp0 = xn0; Xp1 = xn1; Vp0 = vn0; Vp1 = vn1;
                STG128(px, Xp0, Xp1);
                STG128(pv, Vp0, Vp1);
                px += F4SNAP; pv += F4SNAP;
            }
        } else if (lane < SPB && b + 1 < NBATCH) {
            // ========== produce batch b+1 ==========
            const int ph2 = (b + 1) & 1;
            #pragma unroll
            for (int k = 0; k < BATCH; ++k) {
                s_sv[ph2][k][lane] = chain_step();
            }
        }
        __syncthreads();
    }
}

__global__ __launch_bounds__(160, 1)
void nhc_kernel(const float4* __restrict__ gx0,
                const float4* __restrict__ gv0,
                const float*  __restrict__ pkT,
                const float*  __restrict__ pmass,
                const float*  __restrict__ pQ,
                float4*       __restrict__ out)
{
    __shared__ float s_mom[SPB][4];
    __shared__ float s_sv[2][BATCH][SPB];

    const int tid  = threadIdx.x;
    const int lane = tid & 31;
    const int wid  = tid >> 5;                       // 0-3 consumers, 4 producer
    const int base = blockIdx.x * SPB;

    const float kT   = *pkT;
    const float mass = *pmass;
    const float Q    = *pQ;

    // uniform dispatch: literal-constant fast path (FFMA-imm) vs general
    if (kT == 1.0f && mass == 1.0f && Q == 1.0f)
        run_block(1.0f, 1.0f, 1.0f, wid, lane, base, gx0, gv0, out, s_mom, s_sv);
    else
        run_block(kT, mass, Q, wid, lane, base, gx0, gv0, out, s_mom, s_sv);
}

extern "C" void kernel_launch(void* const* d_in, const int* in_sizes, int n_in,
                              void* d_out, int out_size)
{
    const float4* x0   = (const float4*)d_in[0];
    const float4* v0   = (const float4*)d_in[1];
    const float*  kT   = (const float*)d_in[2];
    const float*  mass = (const float*)d_in[3];
    const float*  Q    = (const float*)d_in[4];
    float4* out = (float4*)d_out;

    // 1024 systems / 8 per block = 128 blocks x 160 threads (5 warps):
    // 4 consumer warps + 1 producer warp per block, 1 block/SM on 128 SMs
    nhc_kernel<<<NSYS / SPB, 160>>>(x0, v0, kT, mass, Q, out);
}

// round 16
// speedup vs baseline: 1.6427x; 1.0952x over previous
#include <cuda_runtime.h>

// Nosé–Hoover chain (N_CHAIN=2) velocity-Verlet, B=1024, NDOF=64, 200 steps.
// Out: [traj_x (201,1024,64) | traj_v (201,1024,64)] fp32.
//
// R16 = R5 (best architecture: register-resident fused loop, 2 systems/warp,
// 16 lanes/system, closed 3-moment recursion instead of per-step reductions,
// f32x2 packed elementwise map, STG.128 from packed regs, const-specialized
// kT=mass=Q=1 fast path, 128 blocks x 128 thr = 1 warp/SMSP on 128 SMs)
// + ONE change: trajectory stores use st.global.cs (evict-first streaming).
// Rationale: R5/R14/R15 all pin at ~18us with store payload ~6TB/s and
// L2 ~50% -> the LTS write path is the floor (L2-clock-domain cap, does not
// scale with SM NAT clock). The 105MB write-once stream thrashes L2 under
// default policy (2.4TB/s of mid-kernel HBM eviction); .cs reduces the
// policy-induced pressure on the write path.

namespace {
constexpr int kB     = 1024;
constexpr int kNdof  = 64;
constexpr int kSteps = 200;
constexpr int kF4Sys = kNdof / 4;           // 16 float4 per system
constexpr int kF4Tot = kB * kF4Sys;         // 16384 float4 per snapshot
}

#define FMA2(d,a,b,c) asm("fma.rn.f32x2 %0,%1,%2,%3;" : "=l"(d) : "l"(a), "l"(b), "l"(c))
#define MUL2(d,a,b)   asm("mul.rn.f32x2 %0,%1,%2;"    : "=l"(d) : "l"(a), "l"(b))
#define PACK2(d,f)    asm("mov.b64 %0,{%1,%1};"       : "=l"(d) : "f"(f))
#define PACKAB(d,a,b) asm("mov.b64 %0,{%1,%2};"       : "=l"(d) : "f"(a), "f"(b))
// streaming (evict-first) 128-bit store with compile-time byte offset
#define STG128CS(p,off,a,b) \
    asm volatile("st.global.cs.v2.b64 [%0+" #off "],{%1,%2};" :: "l"(p), "l"(a), "l"(b) : "memory")

// exp(-z) for |z| <= ~3e-4: 1 - z + z^2/2  (rel err ~ z^3/6 <= 5e-12)
__device__ __forceinline__ float expm(float z) {
    return fmaf(fmaf(0.5f, z, -1.0f), z, 1.0f);
}

// Full 200-step loop; with literal kT/mass/Q all coefficients constant-fold
// into FFMA immediates.
__device__ __forceinline__ void nhc_loop(
    float kT, float mass, float Q,
    float sxx, float sxv, float svv,
    unsigned long long Xp0, unsigned long long Xp1,
    unsigned long long Vp0, unsigned long long Vp1,
    const float4* pxc, const float4* pvc)
{
    const float dt    = 0.002f;
    const float dt4   = 0.25f  * dt;
    const float dt8   = 0.125f * dt;
    const float dth   = 0.5f   * dt;
    const float invQ  = 1.0f / Q;
    const float c1    = dth / mass;                  // verlet half-kick coeff
    const float A     = 1.0f - dt * c1;              // constant x coefficient
    const float A2    = A * A;
    const float cx0   = -c1 * (1.0f + A);            // Cx = cx0 * sv
    const float mIQ   = mass * invQ;
    const float nkIQ  = -(float)kNdof * kT * invQ;
    const float kTiQ  = kT * invQ;
    const float m0c   = cx0 * cx0;                   // svv' coeffs
    const float m1c   = 2.0f * cx0 * A;
    const float p1c   = 2.0f * A * dt;               // sxx' coeffs
    const float p2c   = dt * dt;
    const float acx   = A * cx0;                     // sxv' coeffs
    const float mc    = A2 + dt * cx0;               // A*Cv + B*Cx = mc * sv2
    const float dA    = dt * A;

    unsigned long long Ap;
    PACK2(Ap, A);

    float xi0 = 0.0f, xi1 = 0.0f;

    for (int step = 0; step < kSteps; step += 2) {
        #pragma unroll
        for (int u = 0; u < 2; ++u) {
            // ---- first half chain ----
            float G  = fmaf(mIQ, svv, nkIQ);
            xi1 = fmaf(dt4, G, xi1);
            float G0 = fmaf(xi0, xi0, -kTiQ);
            float z1 = xi1 * dt8;
            float s  = expm(z1);
            float s2 = s * s;
            float dt4s = dt4 * s;
            float xi0a = fmaf(xi0, s2, G0 * dt4s);
            float z0 = xi0a * dth;
            float sv  = expm(z0);
            float sv2 = sv * sv;

            // ---- Svv' (only sv/sv2 on the critical path) ----
            float m0 = m0c * sxx;
            float m1 = m1c * sxv;
            float m2 = A2  * svv;
            float svv_n = sv2 * fmaf(sv2, m2, fmaf(sv, m1, m0));

            // ---- second half chain ----
            float G2 = fmaf(mIQ, svv_n, nkIQ);
            xi0 = fmaf(dt4s, G2, xi0a * s2);
            float G3 = fmaf(xi0, xi0, -kTiQ);
            xi1 = fmaf(dt4, G3, xi1);

            // ---- remaining moments ----
            float sxx_n = fmaf(p2c * sv2, svv, fmaf(p1c * sv, sxv, A2 * sxx));
            float t    = acx * sv;                     // A*Cx
            float midm = mc * sv2;                     // A*Cv + B*Cx
            float bcv  = (dA * sv) * sv2;              // B*Cv
            float sxv_n = fmaf(bcv, svv, fmaf(midm, sxv, t * sxx));
            sxx = sxx_n; sxv = sxv_n; svv = svv_n;

            // ---- elementwise linear map (f32x2) ----
            float B  = dt  * sv;
            float Cx = cx0 * sv;
            float Cv = A   * sv2;
            unsigned long long Bp, Cxp, Cvp, t0, t1, u0, u1, xn0, xn1, vn0, vn1;
            PACK2(Bp, B); PACK2(Cxp, Cx); PACK2(Cvp, Cv);
            MUL2(t0, Bp,  Vp0);  MUL2(t1, Bp,  Vp1);
            MUL2(u0, Cvp, Vp0);  MUL2(u1, Cvp, Vp1);
            FMA2(xn0, Ap,  Xp0, t0);  FMA2(xn1, Ap,  Xp1, t1);
            FMA2(vn0, Cxp, Xp0, u0);  FMA2(vn1, Cxp, Xp1, u1);
            Xp0 = xn0; Xp1 = xn1; Vp0 = vn0; Vp1 = vn1;

            // ---- trajectory stores (streaming, evict-first) ----
            if (u == 0) {
                STG128CS(pxc, 0, Xp0, Xp1);
                STG128CS(pvc, 0, Vp0, Vp1);
            } else {
                STG128CS(pxc, 262144, Xp0, Xp1);   // + one snapshot (bytes)
                STG128CS(pvc, 262144, Vp0, Vp1);
            }
        }
        pxc += 2 * kF4Tot; pvc += 2 * kF4Tot;
    }
}

__global__ __launch_bounds__(128, 1)
void nhc_kernel(const float4* __restrict__ gx0,
                const float4* __restrict__ gv0,
                const float*  __restrict__ pkT,
                const float*  __restrict__ pmass,
                const float*  __restrict__ pQ,
                float4*       __restrict__ out)
{
    const int tid = threadIdx.x;
    const int ls  = tid & 15;                        // lane-in-system
    const int b   = blockIdx.x * 8 + (tid >> 4);     // system id < 1024

    const float kT   = *pkT;
    const float mass = *pmass;
    const float Q    = *pQ;

    const int idx = b * kF4Sys + ls;                 // float4 slot

    const float4 x0 = gx0[idx];
    const float4 v0 = gv0[idx];

    const float4* pxc = out + idx;
    const float4* pvc = out + (size_t)(kSteps + 1) * kF4Tot + idx;

    // ---- initial moments (one-time 16-lane reduction) ----
    float sxx, sxv, svv;
    {
        float a = x0.x * x0.x; a = fmaf(x0.y, x0.y, a); a = fmaf(x0.z, x0.z, a); a = fmaf(x0.w, x0.w, a);
        float c = x0.x * v0.x; c = fmaf(x0.y, v0.y, c); c = fmaf(x0.z, v0.z, c); c = fmaf(x0.w, v0.w, c);
        float e = v0.x * v0.x; e = fmaf(v0.y, v0.y, e); e = fmaf(v0.z, v0.z, e); e = fmaf(v0.w, v0.w, e);
        #pragma unroll
        for (int m = 1; m <= 8; m <<= 1) {
            a += __shfl_xor_sync(0xffffffffu, a, m);
            c += __shfl_xor_sync(0xffffffffu, c, m);
            e += __shfl_xor_sync(0xffffffffu, e, m);
        }
        sxx = a; sxv = c; svv = e;
    }

    // ---- pack state ----
    unsigned long long Xp0, Xp1, Vp0, Vp1;
    PACKAB(Xp0, x0.x, x0.y); PACKAB(Xp1, x0.z, x0.w);
    PACKAB(Vp0, v0.x, v0.y); PACKAB(Vp1, v0.z, v0.w);

    // step-0 snapshot
    STG128CS(pxc, 0, Xp0, Xp1);
    STG128CS(pvc, 0, Vp0, Vp1);
    pxc += kF4Tot; pvc += kF4Tot;

    // ---- uniform dispatch: literal-constant fast path vs general ----
    if (kT == 1.0f && mass == 1.0f && Q == 1.0f) {
        nhc_loop(1.0f, 1.0f, 1.0f, sxx, sxv, svv, Xp0, Xp1, Vp0, Vp1, pxc, pvc);
    } else {
        nhc_loop(kT, mass, Q, sxx, sxv, svv, Xp0, Xp1, Vp0, Vp1, pxc, pvc);
    }
}

extern "C" void kernel_launch(void* const* d_in, const int* in_sizes, int n_in,
                              void* d_out, int out_size)
{
    const float4* x0   = (const float4*)d_in[0];
    const float4* v0   = (const float4*)d_in[1];
    const float*  kT   = (const float*)d_in[2];
    const float*  mass = (const float*)d_in[3];
    const float*  Q    = (const float*)d_in[4];
    float4* out = (float4*)d_out;

    // 1024 systems, 2/warp -> 512 warps; 128 blocks x 128 threads:
    // 4 warps/SM on 128 SMs = 1 warp per SMSP (R5 proven-best shape)
    nhc_kernel<<<kB / 8, 128>>>(x0, v0, kT, mass, Q, out);
}